// round 6
// baseline (speedup 1.0000x reference)
#include <cuda_runtime.h>

// y[b, i] = input[b, i] * diag(weight)[i] + bias[i]
// B = 8192, N = 4096, fp32.
//
// Kernel 1: gather diag(weight) -> __device__ scratch (free, hides in launch gap).
// Kernel 2: persistent grid-stride streamer. 888 CTAs (~6/SM) stay resident;
//   each iteration front-batches 8 independent float4 loads (MLP=8).
//   Input/output use streaming (.cs) hints; diag/bias stay default-cached.

#define N_COLS 4096
#define N4 (N_COLS / 4)          // 1024 float4 columns
#define THREADS 256
#define UNROLL 8
#define GRID_CTAS 888            // ~6 CTAs per SM on 148-SM sm_100a

__device__ float g_diag[N_COLS];

__global__ void extract_diag_kernel(const float* __restrict__ weight, int n) {
    int i = blockIdx.x * blockDim.x + threadIdx.x;
    if (i < n) {
        g_diag[i] = weight[(size_t)i * (size_t)(n + 1)];
    }
}

__global__ void __launch_bounds__(THREADS)
scale_bias_kernel(const float4* __restrict__ in,
                  const float4* __restrict__ bias4,
                  float4* __restrict__ out,
                  int total4) {
    const float4* __restrict__ d4 = reinterpret_cast<const float4*>(g_diag);

    int tid0   = blockIdx.x * THREADS + threadIdx.x;
    int stride = GRID_CTAS * THREADS;           // threads in grid
    int step   = stride * UNROLL;

    int base;
    // Main full-unroll passes (no bounds checks inside).
    for (base = tid0; base + (UNROLL - 1) * stride < total4; base += step) {
        float4 x[UNROLL];
        #pragma unroll
        for (int k = 0; k < UNROLL; k++) {
            x[k] = __ldcs(&in[base + k * stride]);    // streaming load, MLP=8
        }
        #pragma unroll
        for (int k = 0; k < UNROLL; k++) {
            int idx = base + k * stride;
            int c = idx & (N4 - 1);
            float4 d = d4[c];                         // L1/L2-resident table
            float4 b = bias4[c];
            float4 y;
            y.x = fmaf(x[k].x, d.x, b.x);
            y.y = fmaf(x[k].y, d.y, b.y);
            y.z = fmaf(x[k].z, d.z, b.z);
            y.w = fmaf(x[k].w, d.w, b.w);
            __stcs(&out[idx], y);                     // streaming store
        }
    }
    // Tail.
    for (; base < total4; base += stride) {
        int c = base & (N4 - 1);
        float4 x = __ldcs(&in[base]);
        float4 d = d4[c];
        float4 b = bias4[c];
        float4 y;
        y.x = fmaf(x.x, d.x, b.x);
        y.y = fmaf(x.y, d.y, b.y);
        y.z = fmaf(x.z, d.z, b.z);
        y.w = fmaf(x.w, d.w, b.w);
        __stcs(&out[base], y);
    }
}

extern "C" void kernel_launch(void* const* d_in, const int* in_sizes, int n_in,
                              void* d_out, int out_size) {
    const float* input  = (const float*)d_in[0];   // [B, N]
    const float* weight = (const float*)d_in[1];   // [N, N]
    const float* bias   = (const float*)d_in[2];   // [N]
    float* out = (float*)d_out;

    // 1) gather diagonal
    extract_diag_kernel<<<(N_COLS + 255) / 256, 256>>>(weight, N_COLS);

    // 2) persistent streaming scale + bias
    int total4 = out_size / 4;                     // B * N4 = 2^23
    scale_bias_kernel<<<GRID_CTAS, THREADS>>>(
        reinterpret_cast<const float4*>(input),
        reinterpret_cast<const float4*>(bias),
        reinterpret_cast<float4*>(out),
        total4);
}

// round 8
// speedup vs baseline: 1.1202x; 1.1202x over previous
#include <cuda_runtime.h>

// y[b, i] = input[b, i] * diag(weight)[i] + bias[i]
// B = 8192, N = 4096, fp32.
//
// Kernel 1: gather diag(weight) -> __device__ scratch (tiny).
// Kernel 2: R3-style wide-stride streamer, MLP=4. Grid sized so each thread
//   does EXACTLY 4 float4s (no bounds checks, no tail): the 4 accesses are
//   idx + k*gridstride, all warp-coalesced LDG.128/STG.128. Default caching.

#define N_COLS 4096
#define N4 (N_COLS / 4)          // 1024 float4 columns
#define THREADS 256
#define UNROLL 4

__device__ float g_diag[N_COLS];

__global__ void extract_diag_kernel(const float* __restrict__ weight, int n) {
    int i = blockIdx.x * blockDim.x + threadIdx.x;
    if (i < n) {
        g_diag[i] = weight[(size_t)i * (size_t)(n + 1)];
    }
}

__global__ void __launch_bounds__(THREADS)
scale_bias_kernel(const float4* __restrict__ in,
                  const float4* __restrict__ bias4,
                  float4* __restrict__ out) {
    const float4* __restrict__ d4 = reinterpret_cast<const float4*>(g_diag);

    int idx0   = blockIdx.x * THREADS + threadIdx.x;
    int stride = gridDim.x * THREADS;      // grid covers total4/UNROLL exactly

    // Front-batched independent loads (MLP = 4), default caching.
    float4 x[UNROLL];
    #pragma unroll
    for (int k = 0; k < UNROLL; k++) {
        x[k] = in[idx0 + k * stride];
    }

    #pragma unroll
    for (int k = 0; k < UNROLL; k++) {
        int idx = idx0 + k * stride;
        int c = idx & (N4 - 1);            // column (N4 power of two)
        float4 d = d4[c];                  // 16 KB table, L1-resident
        float4 b = bias4[c];               // 16 KB table, L1-resident
        float4 y;
        y.x = fmaf(x[k].x, d.x, b.x);
        y.y = fmaf(x[k].y, d.y, b.y);
        y.z = fmaf(x[k].z, d.z, b.z);
        y.w = fmaf(x[k].w, d.w, b.w);
        out[idx] = y;
    }
}

extern "C" void kernel_launch(void* const* d_in, const int* in_sizes, int n_in,
                              void* d_out, int out_size) {
    const float* input  = (const float*)d_in[0];   // [B, N]
    const float* weight = (const float*)d_in[1];   // [N, N]
    const float* bias   = (const float*)d_in[2];   // [N]
    float* out = (float*)d_out;

    // 1) gather diagonal
    extract_diag_kernel<<<(N_COLS + 255) / 256, 256>>>(weight, N_COLS);

    // 2) wide-stride streamer: total4 = B*N/4 = 2^23, divides exactly.
    int total4 = out_size / 4;
    int blocks = total4 / (THREADS * UNROLL);      // 8192
    scale_bias_kernel<<<blocks, THREADS>>>(
        reinterpret_cast<const float4*>(input),
        reinterpret_cast<const float4*>(bias),
        reinterpret_cast<float4*>(out));
}